// round 1
// baseline (speedup 1.0000x reference)
#include <cuda_runtime.h>
#include <math.h>

// Problem constants
#define BB  4
#define SS  2048
#define DD  1024
#define HH  16
#define DK  64

// ---------------------------------------------------------------------------
// Scratch (allocated at module load; no runtime allocation)
// ---------------------------------------------------------------------------
__device__ float g_q[BB * SS * DD];
__device__ float g_k[BB * SS * DD];
__device__ float g_v[BB * SS * DD];
__device__ float g_o[BB * SS * DD];

// ---------------------------------------------------------------------------
// C[M,N] = A[M,K] @ W[N,K]^T + bias[N]
// 128x128 block, BK=16, 8x8 microtile, 256 threads.
// M,N,K all multiples of 128/16 for this problem -> no bounds checks.
// ---------------------------------------------------------------------------
__global__ __launch_bounds__(256) void gemm_nt_bias(
    const float* __restrict__ A,
    const float* __restrict__ W,
    const float* __restrict__ bias,
    float* __restrict__ C,
    int M, int N, int K)
{
    __shared__ float As[16][132];
    __shared__ float Ws[16][132];

    const int tid = threadIdx.x;
    const int tx  = tid & 15;          // 0..15 (N dir)
    const int ty  = tid >> 4;          // 0..15 (M dir)
    const int bm  = blockIdx.y * 128;
    const int bn  = blockIdx.x * 128;

    const int lrow = tid >> 2;         // 0..63
    const int lcol = (tid & 3) * 4;    // 0,4,8,12

    const float* Ab = A + (size_t)bm * K;
    const float* Wb = W + (size_t)bn * K;

    float acc[8][8];
    #pragma unroll
    for (int i = 0; i < 8; i++)
        #pragma unroll
        for (int j = 0; j < 8; j++)
            acc[i][j] = 0.0f;

    for (int k0 = 0; k0 < K; k0 += 16) {
        float4 a0 = *(const float4*)(Ab + (size_t)lrow        * K + k0 + lcol);
        float4 a1 = *(const float4*)(Ab + (size_t)(lrow + 64) * K + k0 + lcol);
        float4 w0 = *(const float4*)(Wb + (size_t)lrow        * K + k0 + lcol);
        float4 w1 = *(const float4*)(Wb + (size_t)(lrow + 64) * K + k0 + lcol);

        __syncthreads();
        As[lcol + 0][lrow]      = a0.x;
        As[lcol + 1][lrow]      = a0.y;
        As[lcol + 2][lrow]      = a0.z;
        As[lcol + 3][lrow]      = a0.w;
        As[lcol + 0][lrow + 64] = a1.x;
        As[lcol + 1][lrow + 64] = a1.y;
        As[lcol + 2][lrow + 64] = a1.z;
        As[lcol + 3][lrow + 64] = a1.w;
        Ws[lcol + 0][lrow]      = w0.x;
        Ws[lcol + 1][lrow]      = w0.y;
        Ws[lcol + 2][lrow]      = w0.z;
        Ws[lcol + 3][lrow]      = w0.w;
        Ws[lcol + 0][lrow + 64] = w1.x;
        Ws[lcol + 1][lrow + 64] = w1.y;
        Ws[lcol + 2][lrow + 64] = w1.z;
        Ws[lcol + 3][lrow + 64] = w1.w;
        __syncthreads();

        #pragma unroll
        for (int kk = 0; kk < 16; kk++) {
            float af[8], wf[8];
            *(float4*)(af)     = *(const float4*)(&As[kk][ty * 8]);
            *(float4*)(af + 4) = *(const float4*)(&As[kk][ty * 8 + 4]);
            *(float4*)(wf)     = *(const float4*)(&Ws[kk][tx * 8]);
            *(float4*)(wf + 4) = *(const float4*)(&Ws[kk][tx * 8 + 4]);
            #pragma unroll
            for (int i = 0; i < 8; i++)
                #pragma unroll
                for (int j = 0; j < 8; j++)
                    acc[i][j] = fmaf(af[i], wf[j], acc[i][j]);
        }
    }

    #pragma unroll
    for (int i = 0; i < 8; i++) {
        size_t crow = (size_t)(bm + ty * 8 + i) * N + bn + tx * 8;
        #pragma unroll
        for (int j = 0; j < 8; j += 4) {
            float4 o;
            o.x = acc[i][j + 0] + bias[bn + tx * 8 + j + 0];
            o.y = acc[i][j + 1] + bias[bn + tx * 8 + j + 1];
            o.z = acc[i][j + 2] + bias[bn + tx * 8 + j + 2];
            o.w = acc[i][j + 3] + bias[bn + tx * 8 + j + 3];
            *(float4*)(C + crow + j) = o;
        }
    }
}

// ---------------------------------------------------------------------------
// Fused flash attention.
// Block = (b, h, 64 q-rows). 256 threads as 16(ty: rows)x16(tx: cols),
// each thread owns a 4x4 microtile of the 64x64 score tile and a 4x4
// microtile of the 64(dk) output accumulator.
// q and k staged transposed (dk-major) in smem for vectorized fragment loads.
// Online softmax with shfl reductions over the 16 tx lanes (intra-warp).
// ---------------------------------------------------------------------------
#define ATT_STRIDE 68   // 64 + 4 pad, multiple of 4 for float4 smem ops
#define ATT_SMEM_BYTES (4 * 64 * ATT_STRIDE * 4)

__global__ __launch_bounds__(256) void attn_kernel(
    const int*   __restrict__ mask,    // [B,1,S,S]
    const float* __restrict__ abias)   // [1,H,S,S]
{
    extern __shared__ float sm[];
    float* qst = sm;                       // [64 dk][68] (dk-major)
    float* kst = sm + 64 * ATT_STRIDE;     // [64 dk][68] (dk-major)
    float* vs  = sm + 2 * 64 * ATT_STRIDE; // [64 kpos][68] (kpos-major)
    float* ps  = sm + 3 * 64 * ATT_STRIDE; // [64 qrow][68]

    const int tid = threadIdx.x;
    const int tx  = tid & 15;
    const int ty  = tid >> 4;
    const int q0  = blockIdx.x * 64;
    const int h   = blockIdx.y;
    const int b   = blockIdx.z;

    // Load Q tile (64 rows x 64 dk), stored transposed
    {
        const float* qg = g_q + ((size_t)b * SS + q0) * DD + h * DK;
        #pragma unroll
        for (int it = 0; it < 4; it++) {
            int i   = tid + it * 256;
            int row = i >> 4;
            int c4  = (i & 15) * 4;
            float4 v = *(const float4*)(qg + (size_t)row * DD + c4);
            qst[(c4 + 0) * ATT_STRIDE + row] = v.x;
            qst[(c4 + 1) * ATT_STRIDE + row] = v.y;
            qst[(c4 + 2) * ATT_STRIDE + row] = v.z;
            qst[(c4 + 3) * ATT_STRIDE + row] = v.w;
        }
    }

    float m_i[4], l_i[4], acc[4][4];
    #pragma unroll
    for (int i = 0; i < 4; i++) {
        m_i[i] = -1e30f;
        l_i[i] = 0.0f;
        #pragma unroll
        for (int j = 0; j < 4; j++) acc[i][j] = 0.0f;
    }

    for (int kt = 0; kt < SS / 64; kt++) {
        const int k0 = kt * 64;
        const float* kg = g_k + ((size_t)b * SS + k0) * DD + h * DK;
        const float* vg = g_v + ((size_t)b * SS + k0) * DD + h * DK;

        __syncthreads();   // protect kst/vs/ps from previous iteration's readers
        #pragma unroll
        for (int it = 0; it < 4; it++) {
            int i   = tid + it * 256;
            int row = i >> 4;
            int c4  = (i & 15) * 4;
            float4 kv = *(const float4*)(kg + (size_t)row * DD + c4);
            kst[(c4 + 0) * ATT_STRIDE + row] = kv.x;
            kst[(c4 + 1) * ATT_STRIDE + row] = kv.y;
            kst[(c4 + 2) * ATT_STRIDE + row] = kv.z;
            kst[(c4 + 3) * ATT_STRIDE + row] = kv.w;
            float4 vv = *(const float4*)(vg + (size_t)row * DD + c4);
            *(float4*)(vs + row * ATT_STRIDE + c4) = vv;
        }
        __syncthreads();

        // S = Q K^T for this tile
        float s[4][4];
        #pragma unroll
        for (int i = 0; i < 4; i++)
            #pragma unroll
            for (int j = 0; j < 4; j++) s[i][j] = 0.0f;

        #pragma unroll 8
        for (int dk = 0; dk < 64; dk++) {
            float4 aq = *(const float4*)(qst + dk * ATT_STRIDE + ty * 4);
            float4 bk = *(const float4*)(kst + dk * ATT_STRIDE + tx * 4);
            s[0][0] = fmaf(aq.x, bk.x, s[0][0]);
            s[0][1] = fmaf(aq.x, bk.y, s[0][1]);
            s[0][2] = fmaf(aq.x, bk.z, s[0][2]);
            s[0][3] = fmaf(aq.x, bk.w, s[0][3]);
            s[1][0] = fmaf(aq.y, bk.x, s[1][0]);
            s[1][1] = fmaf(aq.y, bk.y, s[1][1]);
            s[1][2] = fmaf(aq.y, bk.z, s[1][2]);
            s[1][3] = fmaf(aq.y, bk.w, s[1][3]);
            s[2][0] = fmaf(aq.z, bk.x, s[2][0]);
            s[2][1] = fmaf(aq.z, bk.y, s[2][1]);
            s[2][2] = fmaf(aq.z, bk.z, s[2][2]);
            s[2][3] = fmaf(aq.z, bk.w, s[2][3]);
            s[3][0] = fmaf(aq.w, bk.x, s[3][0]);
            s[3][1] = fmaf(aq.w, bk.y, s[3][1]);
            s[3][2] = fmaf(aq.w, bk.z, s[3][2]);
            s[3][3] = fmaf(aq.w, bk.w, s[3][3]);
        }

        // mask, bias, online softmax update (per owned row)
        const float scale = 0.125f;   // 1/sqrt(64)
        #pragma unroll
        for (int i = 0; i < 4; i++) {
            const int qrow = q0 + ty * 4 + i;
            int4   mr = *(const int4*)  (mask  + ((size_t)b * SS + qrow) * SS + k0 + tx * 4);
            float4 br = *(const float4*)(abias + ((size_t)h * SS + qrow) * SS + k0 + tx * 4);
            s[i][0] = (mr.x != 0 ? s[i][0] * scale : -1e9f) + br.x;
            s[i][1] = (mr.y != 0 ? s[i][1] * scale : -1e9f) + br.y;
            s[i][2] = (mr.z != 0 ? s[i][2] * scale : -1e9f) + br.z;
            s[i][3] = (mr.w != 0 ? s[i][3] * scale : -1e9f) + br.w;

            float mt = fmaxf(fmaxf(s[i][0], s[i][1]), fmaxf(s[i][2], s[i][3]));
            #pragma unroll
            for (int o = 1; o < 16; o <<= 1)
                mt = fmaxf(mt, __shfl_xor_sync(0xffffffffu, mt, o));

            float mn   = fmaxf(m_i[i], mt);
            float corr = __expf(m_i[i] - mn);
            m_i[i] = mn;

            float lt = 0.0f;
            #pragma unroll
            for (int j = 0; j < 4; j++) {
                s[i][j] = __expf(s[i][j] - mn);
                lt += s[i][j];
            }
            #pragma unroll
            for (int o = 1; o < 16; o <<= 1)
                lt += __shfl_xor_sync(0xffffffffu, lt, o);

            l_i[i] = l_i[i] * corr + lt;
            acc[i][0] *= corr;
            acc[i][1] *= corr;
            acc[i][2] *= corr;
            acc[i][3] *= corr;
        }

        // stage P tile in smem
        #pragma unroll
        for (int i = 0; i < 4; i++) {
            float4 pv = make_float4(s[i][0], s[i][1], s[i][2], s[i][3]);
            *(float4*)(ps + (ty * 4 + i) * ATT_STRIDE + tx * 4) = pv;
        }
        __syncthreads();

        // O += P V
        #pragma unroll 8
        for (int k = 0; k < 64; k++) {
            float4 vv = *(const float4*)(vs + k * ATT_STRIDE + tx * 4);
            float p0 = ps[(ty * 4 + 0) * ATT_STRIDE + k];
            float p1 = ps[(ty * 4 + 1) * ATT_STRIDE + k];
            float p2 = ps[(ty * 4 + 2) * ATT_STRIDE + k];
            float p3 = ps[(ty * 4 + 3) * ATT_STRIDE + k];
            acc[0][0] = fmaf(p0, vv.x, acc[0][0]);
            acc[0][1] = fmaf(p0, vv.y, acc[0][1]);
            acc[0][2] = fmaf(p0, vv.z, acc[0][2]);
            acc[0][3] = fmaf(p0, vv.w, acc[0][3]);
            acc[1][0] = fmaf(p1, vv.x, acc[1][0]);
            acc[1][1] = fmaf(p1, vv.y, acc[1][1]);
            acc[1][2] = fmaf(p1, vv.z, acc[1][2]);
            acc[1][3] = fmaf(p1, vv.w, acc[1][3]);
            acc[2][0] = fmaf(p2, vv.x, acc[2][0]);
            acc[2][1] = fmaf(p2, vv.y, acc[2][1]);
            acc[2][2] = fmaf(p2, vv.z, acc[2][2]);
            acc[2][3] = fmaf(p2, vv.w, acc[2][3]);
            acc[3][0] = fmaf(p3, vv.x, acc[3][0]);
            acc[3][1] = fmaf(p3, vv.y, acc[3][1]);
            acc[3][2] = fmaf(p3, vv.z, acc[3][2]);
            acc[3][3] = fmaf(p3, vv.w, acc[3][3]);
        }
    }

    // normalize and write attention output [B,S,D]
    #pragma unroll
    for (int i = 0; i < 4; i++) {
        float inv = 1.0f / l_i[i];
        float4 o = make_float4(acc[i][0] * inv, acc[i][1] * inv,
                               acc[i][2] * inv, acc[i][3] * inv);
        *(float4*)(g_o + ((size_t)b * SS + (q0 + ty * 4 + i)) * DD + h * DK + tx * 4) = o;
    }
}

// ---------------------------------------------------------------------------
// Launch
// ---------------------------------------------------------------------------
extern "C" void kernel_launch(void* const* d_in, const int* in_sizes, int n_in,
                              void* d_out, int out_size)
{
    const float* Q     = (const float*)d_in[0];
    const float* K     = (const float*)d_in[1];
    const float* V     = (const float*)d_in[2];
    const int*   mask  = (const int*)  d_in[3];
    const float* abias = (const float*)d_in[4];
    const float* Wq    = (const float*)d_in[5];
    const float* bq    = (const float*)d_in[6];
    const float* Wk    = (const float*)d_in[7];
    const float* bk    = (const float*)d_in[8];
    const float* Wv    = (const float*)d_in[9];
    const float* bv    = (const float*)d_in[10];
    const float* Wo    = (const float*)d_in[11];
    const float* bo    = (const float*)d_in[12];
    float* out = (float*)d_out;

    float *qb, *kb, *vb, *ob;
    cudaGetSymbolAddress((void**)&qb, g_q);
    cudaGetSymbolAddress((void**)&kb, g_k);
    cudaGetSymbolAddress((void**)&vb, g_v);
    cudaGetSymbolAddress((void**)&ob, g_o);

    cudaFuncSetAttribute(attn_kernel,
                         cudaFuncAttributeMaxDynamicSharedMemorySize,
                         ATT_SMEM_BYTES);

    const int M = BB * SS;   // 8192
    dim3 ggrid(DD / 128, M / 128);   // (8, 64)

    gemm_nt_bias<<<ggrid, 256>>>(Q, Wq, bq, qb, M, DD, DD);
    gemm_nt_bias<<<ggrid, 256>>>(K, Wk, bk, kb, M, DD, DD);
    gemm_nt_bias<<<ggrid, 256>>>(V, Wv, bv, vb, M, DD, DD);

    attn_kernel<<<dim3(SS / 64, HH, BB), 256, ATT_SMEM_BYTES>>>(mask, abias);

    gemm_nt_bias<<<ggrid, 256>>>(ob, Wo, bo, out, M, DD, DD);
}

// round 3
// speedup vs baseline: 2.0820x; 2.0820x over previous
#include <cuda_runtime.h>
#include <cuda_bf16.h>
#include <stdint.h>

#define BB 4
#define SS 2048
#define DD 1024
#define HH 16
#define MM (BB*SS)   // 8192

// ---------------------------------------------------------------------------
// Scratch (static device globals; no runtime allocation)
// ---------------------------------------------------------------------------
__device__ __nv_bfloat16 g_ah[MM*DD], g_al[MM*DD];   // activation hi/lo (reused)
__device__ __nv_bfloat16 g_wh[DD*DD], g_wl[DD*DD];   // weight hi/lo (reused)
__device__ __nv_bfloat16 g_qh[MM*DD], g_ql[MM*DD];
__device__ __nv_bfloat16 g_kh[MM*DD], g_kl[MM*DD];
__device__ __nv_bfloat16 g_vh[MM*DD], g_vl[MM*DD];
__device__ __nv_bfloat16 g_oh[MM*DD], g_ol[MM*DD];

// ---------------------------------------------------------------------------
// PTX helpers
// ---------------------------------------------------------------------------
__device__ __forceinline__ void cpa16(void* s, const void* g) {
    uint32_t sa = (uint32_t)__cvta_generic_to_shared(s);
    asm volatile("cp.async.ca.shared.global [%0], [%1], 16;\n" :: "r"(sa), "l"(g));
}
__device__ __forceinline__ void cp_commit() { asm volatile("cp.async.commit_group;\n" ::); }
template<int N> __device__ __forceinline__ void cp_wait() {
    asm volatile("cp.async.wait_group %0;\n" :: "n"(N));
}
__device__ __forceinline__ void ldsm4(uint32_t* r, const void* p) {
    uint32_t a = (uint32_t)__cvta_generic_to_shared(p);
    asm volatile("ldmatrix.sync.aligned.m8n8.x4.shared.b16 {%0,%1,%2,%3}, [%4];\n"
                 : "=r"(r[0]), "=r"(r[1]), "=r"(r[2]), "=r"(r[3]) : "r"(a));
}
__device__ __forceinline__ void ldsm2(uint32_t* r, const void* p) {
    uint32_t a = (uint32_t)__cvta_generic_to_shared(p);
    asm volatile("ldmatrix.sync.aligned.m8n8.x2.shared.b16 {%0,%1}, [%2];\n"
                 : "=r"(r[0]), "=r"(r[1]) : "r"(a));
}
__device__ __forceinline__ void ldsm2t(uint32_t* r, const void* p) {
    uint32_t a = (uint32_t)__cvta_generic_to_shared(p);
    asm volatile("ldmatrix.sync.aligned.m8n8.x2.trans.shared.b16 {%0,%1}, [%2];\n"
                 : "=r"(r[0]), "=r"(r[1]) : "r"(a));
}
__device__ __forceinline__ void mma16816(float* c, const uint32_t* a, const uint32_t* b) {
    asm volatile(
        "mma.sync.aligned.m16n8k16.row.col.f32.bf16.bf16.f32 "
        "{%0,%1,%2,%3}, {%4,%5,%6,%7}, {%8,%9}, {%0,%1,%2,%3};\n"
        : "+f"(c[0]), "+f"(c[1]), "+f"(c[2]), "+f"(c[3])
        : "r"(a[0]), "r"(a[1]), "r"(a[2]), "r"(a[3]), "r"(b[0]), "r"(b[1]));
}
__device__ __forceinline__ uint32_t packsplit(float x0, float x1, uint32_t& lo) {
    __nv_bfloat16 h0 = __float2bfloat16(x0), h1 = __float2bfloat16(x1);
    __nv_bfloat16 l0 = __float2bfloat16(x0 - __bfloat162float(h0));
    __nv_bfloat16 l1 = __float2bfloat16(x1 - __bfloat162float(h1));
    __nv_bfloat162 hp = __halves2bfloat162(h0, h1);
    __nv_bfloat162 lp = __halves2bfloat162(l0, l1);
    lo = *(uint32_t*)&lp;
    return *(uint32_t*)&hp;
}

// ---------------------------------------------------------------------------
// fp32 -> bf16 hi/lo split (elementwise)
// ---------------------------------------------------------------------------
__global__ __launch_bounds__(256) void split_bf16(
    const float* __restrict__ x,
    __nv_bfloat16* __restrict__ hi, __nv_bfloat16* __restrict__ lo, int n4)
{
    int i = blockIdx.x * 256 + threadIdx.x;
    if (i >= n4) return;
    float4 v = ((const float4*)x)[i];
    uint32_t l0, l1;
    uint32_t h0 = packsplit(v.x, v.y, l0);
    uint32_t h1 = packsplit(v.z, v.w, l1);
    ((uint32_t*)hi)[i*2+0] = h0; ((uint32_t*)hi)[i*2+1] = h1;
    ((uint32_t*)lo)[i*2+0] = l0; ((uint32_t*)lo)[i*2+1] = l1;
}

// ---------------------------------------------------------------------------
// C[M,1024] = A[M,1024] @ W[1024,1024]^T + bias ; 3-pass split-bf16 tensor GEMM
// 128x128 tile, BK=32, 256 threads (8 warps 2m x 4n, warp = 64x32).
// ---------------------------------------------------------------------------
#define GST 40
#define GARR (128*GST)
#define GSTAGE (4*GARR)
#define GEMM_SMEM (2*GSTAGE*2)   // 81920 bytes

template<int OUT_BF16>
__global__ __launch_bounds__(256) void gemm3(
    const __nv_bfloat16* __restrict__ Ah, const __nv_bfloat16* __restrict__ Al,
    const __nv_bfloat16* __restrict__ Wh, const __nv_bfloat16* __restrict__ Wl,
    const float* __restrict__ bias, float* __restrict__ C,
    __nv_bfloat16* __restrict__ Ch, __nv_bfloat16* __restrict__ Cl)
{
    extern __shared__ __nv_bfloat16 sg[];
    const int tid = threadIdx.x, lane = tid & 31, warp = tid >> 5;
    const int wm = warp >> 2, wn = warp & 3;
    const int bm = blockIdx.y * 128, bn = blockIdx.x * 128;

    float acc[4][4][4];
    #pragma unroll
    for (int i = 0; i < 4; i++)
        #pragma unroll
        for (int j = 0; j < 4; j++)
            #pragma unroll
            for (int q = 0; q < 4; q++) acc[i][j][q] = 0.0f;

    auto issue = [&](int t, int s) {
        __nv_bfloat16* sb = sg + s * GSTAGE;
        const int k0 = t * 32;
        #pragma unroll
        for (int it = 0; it < 2; it++) {
            int lin = tid + it * 256;
            int r = lin >> 2, c = (lin & 3) * 8;
            size_t ga = (size_t)(bm + r) * DD + k0 + c;
            size_t gw = (size_t)(bn + r) * DD + k0 + c;
            __nv_bfloat16* sr = sb + r * GST + c;
            cpa16(sr,          Ah + ga);
            cpa16(sr + GARR,   Al + ga);
            cpa16(sr + 2*GARR, Wh + gw);
            cpa16(sr + 3*GARR, Wl + gw);
        }
    };

    issue(0, 0); cp_commit();

    for (int t = 0; t < DD / 32; t++) {
        if (t + 1 < DD / 32) { issue(t + 1, (t + 1) & 1); cp_commit(); cp_wait<1>(); }
        else                 { cp_wait<0>(); }
        __syncthreads();

        const __nv_bfloat16* sb = sg + (t & 1) * GSTAGE;
        #pragma unroll
        for (int ks = 0; ks < 2; ks++) {
            uint32_t ah[4][4], al[4][4], bh[4][2], bl[4][2];
            #pragma unroll
            for (int mf = 0; mf < 4; mf++) {
                int r = wm * 64 + mf * 16 + (lane & 15);
                int c = ks * 16 + ((lane >> 4) << 3);
                ldsm4(ah[mf], sb + r * GST + c);
                ldsm4(al[mf], sb + GARR + r * GST + c);
            }
            #pragma unroll
            for (int nf = 0; nf < 4; nf++) {
                int r = wn * 32 + nf * 8 + (lane & 7);
                int c = ks * 16 + (((lane >> 3) & 1) << 3);
                ldsm2(bh[nf], sb + 2*GARR + r * GST + c);
                ldsm2(bl[nf], sb + 3*GARR + r * GST + c);
            }
            #pragma unroll
            for (int mf = 0; mf < 4; mf++)
                #pragma unroll
                for (int nf = 0; nf < 4; nf++) {
                    mma16816(acc[mf][nf], ah[mf], bh[nf]);
                    mma16816(acc[mf][nf], ah[mf], bl[nf]);
                    mma16816(acc[mf][nf], al[mf], bh[nf]);
                }
        }
        __syncthreads();
    }

    #pragma unroll
    for (int mf = 0; mf < 4; mf++)
        #pragma unroll
        for (int nf = 0; nf < 4; nf++) {
            int col = bn + wn * 32 + nf * 8 + (lane & 3) * 2;
            float2 bs = *(const float2*)(bias + col);
            #pragma unroll
            for (int p = 0; p < 2; p++) {
                int row = bm + wm * 64 + mf * 16 + (lane >> 2) + p * 8;
                float x0 = acc[mf][nf][p*2+0] + bs.x;
                float x1 = acc[mf][nf][p*2+1] + bs.y;
                if (OUT_BF16) {
                    uint32_t lo, hi = packsplit(x0, x1, lo);
                    *(uint32_t*)(Ch + (size_t)row * DD + col) = hi;
                    *(uint32_t*)(Cl + (size_t)row * DD + col) = lo;
                } else {
                    float2 o; o.x = x0; o.y = x1;
                    *(float2*)(C + (size_t)row * DD + col) = o;
                }
            }
        }
}

// ---------------------------------------------------------------------------
// Fused flash attention, split-bf16 tensor cores.
// Block = (b,h) x 64 q-rows, 128 threads = 4 warps (warp = m16 x n64).
// ---------------------------------------------------------------------------
#define AST 72
#define ATILE (64*AST)
#define ATT_SMEM (10*ATILE*2)   // Qh,Ql + 2 stages x (Kh,Kl,Vh,Vl) = 92160 B

__global__ __launch_bounds__(128) void attn3(
    const int* __restrict__ mask, const float* __restrict__ abias)
{
    extern __shared__ __nv_bfloat16 sa[];
    __nv_bfloat16* Qh = sa;
    __nv_bfloat16* Ql = sa + ATILE;

    const int tid = threadIdx.x, lane = tid & 31, warp = tid >> 5;
    const int h = blockIdx.x >> 2, b = blockIdx.x & 3;
    const int q0 = blockIdx.y * 64;

    const size_t qg = ((size_t)b * SS + q0) * DD + h * 64;
    #pragma unroll
    for (int it = 0; it < 4; it++) {
        int lin = tid + it * 128;
        int r = lin >> 3, c = (lin & 7) * 8;
        cpa16(Qh + r * AST + c, g_qh + qg + (size_t)r * DD + c);
        cpa16(Ql + r * AST + c, g_ql + qg + (size_t)r * DD + c);
    }
    auto issue_kv = [&](int kt, int s) {
        __nv_bfloat16* sb = sa + 2 * ATILE + s * 4 * ATILE;
        const size_t g0 = ((size_t)b * SS + kt * 64) * DD + h * 64;
        #pragma unroll
        for (int it = 0; it < 4; it++) {
            int lin = tid + it * 128;
            int r = lin >> 3, c = (lin & 7) * 8;
            size_t g = g0 + (size_t)r * DD + c;
            __nv_bfloat16* sr = sb + r * AST + c;
            cpa16(sr,           g_kh + g);
            cpa16(sr + ATILE,   g_kl + g);
            cpa16(sr + 2*ATILE, g_vh + g);
            cpa16(sr + 3*ATILE, g_vl + g);
        }
    };
    issue_kv(0, 0); cp_commit();

    float oacc[8][4];
    #pragma unroll
    for (int nf = 0; nf < 8; nf++)
        #pragma unroll
        for (int q = 0; q < 4; q++) oacc[nf][q] = 0.0f;
    float m_i[2] = {-1e30f, -1e30f}, l_i[2] = {0.0f, 0.0f};

    const int rq = q0 + warp * 16 + (lane >> 2);

    for (int kt = 0; kt < SS / 64; kt++) {
        if (kt + 1 < SS / 64) { issue_kv(kt + 1, (kt + 1) & 1); cp_commit(); cp_wait<1>(); }
        else                  { cp_wait<0>(); }
        __syncthreads();

        const __nv_bfloat16* Kh = sa + 2 * ATILE + (kt & 1) * 4 * ATILE;
        const __nv_bfloat16* Kl = Kh + ATILE;
        const __nv_bfloat16* Vh = Kh + 2 * ATILE;
        const __nv_bfloat16* Vl = Kh + 3 * ATILE;

        // ---- S = Q K^T (3-pass) ----
        float sacc[8][4];
        #pragma unroll
        for (int nf = 0; nf < 8; nf++)
            #pragma unroll
            for (int q = 0; q < 4; q++) sacc[nf][q] = 0.0f;

        #pragma unroll
        for (int ks = 0; ks < 4; ks++) {
            uint32_t aqh[4], aql[4];
            int rA = warp * 16 + (lane & 15);
            int cA = ks * 16 + ((lane >> 4) << 3);
            ldsm4(aqh, Qh + rA * AST + cA);
            ldsm4(aql, Ql + rA * AST + cA);
            #pragma unroll
            for (int nf = 0; nf < 8; nf++) {
                uint32_t bh[2], bl[2];
                int rB = nf * 8 + (lane & 7);
                int cB = ks * 16 + (((lane >> 3) & 1) << 3);
                ldsm2(bh, Kh + rB * AST + cB);
                ldsm2(bl, Kl + rB * AST + cB);
                mma16816(sacc[nf], aqh, bh);
                mma16816(sacc[nf], aqh, bl);
                mma16816(sacc[nf], aql, bh);
            }
        }

        // ---- mask + bias + online softmax (fp32, in registers) ----
        float mx[2] = {-1e30f, -1e30f};
        #pragma unroll
        for (int nf = 0; nf < 8; nf++) {
            int col = kt * 64 + nf * 8 + (lane & 3) * 2;
            #pragma unroll
            for (int p = 0; p < 2; p++) {
                int row = rq + p * 8;
                int2   mr = *(const int2*)  (mask  + ((size_t)b * SS + row) * SS + col);
                float2 br = *(const float2*)(abias + ((size_t)h * SS + row) * SS + col);
                float s0 = (mr.x != 0 ? sacc[nf][2*p+0] * 0.125f : -1e9f) + br.x;
                float s1 = (mr.y != 0 ? sacc[nf][2*p+1] * 0.125f : -1e9f) + br.y;
                sacc[nf][2*p+0] = s0;
                sacc[nf][2*p+1] = s1;
                mx[p] = fmaxf(mx[p], fmaxf(s0, s1));
            }
        }
        float corr[2], ls[2];
        #pragma unroll
        for (int p = 0; p < 2; p++) {
            mx[p] = fmaxf(mx[p], __shfl_xor_sync(0xffffffffu, mx[p], 1));
            mx[p] = fmaxf(mx[p], __shfl_xor_sync(0xffffffffu, mx[p], 2));
            float mn = fmaxf(m_i[p], mx[p]);
            corr[p] = __expf(m_i[p] - mn);
            m_i[p] = mn;
            ls[p] = 0.0f;
        }
        #pragma unroll
        for (int nf = 0; nf < 8; nf++)
            #pragma unroll
            for (int q = 0; q < 4; q++) {
                float e = __expf(sacc[nf][q] - m_i[q >> 1]);
                sacc[nf][q] = e;
                ls[q >> 1] += e;
            }
        #pragma unroll
        for (int p = 0; p < 2; p++) {
            ls[p] += __shfl_xor_sync(0xffffffffu, ls[p], 1);
            ls[p] += __shfl_xor_sync(0xffffffffu, ls[p], 2);
            l_i[p] = l_i[p] * corr[p] + ls[p];
        }
        #pragma unroll
        for (int nf = 0; nf < 8; nf++)
            #pragma unroll
            for (int q = 0; q < 4; q++) oacc[nf][q] *= corr[q >> 1];

        // ---- repack P accumulators -> m16k16 A fragments (hi/lo) ----
        uint32_t ph[4][4], pl[4][4];
        #pragma unroll
        for (int kk = 0; kk < 4; kk++) {
            int j = 2 * kk;
            ph[kk][0] = packsplit(sacc[j][0],   sacc[j][1],   pl[kk][0]);
            ph[kk][1] = packsplit(sacc[j][2],   sacc[j][3],   pl[kk][1]);
            ph[kk][2] = packsplit(sacc[j+1][0], sacc[j+1][1], pl[kk][2]);
            ph[kk][3] = packsplit(sacc[j+1][2], sacc[j+1][3], pl[kk][3]);
        }

        // ---- O += P V (3-pass) ----
        #pragma unroll
        for (int kk = 0; kk < 4; kk++) {
            int rV = kk * 16 + (lane & 7) + (((lane >> 3) & 1) << 3);
            #pragma unroll
            for (int nf = 0; nf < 8; nf++) {
                uint32_t vh2[2], vl2[2];
                ldsm2t(vh2, Vh + rV * AST + nf * 8);
                ldsm2t(vl2, Vl + rV * AST + nf * 8);
                mma16816(oacc[nf], ph[kk], vh2);
                mma16816(oacc[nf], ph[kk], vl2);
                mma16816(oacc[nf], pl[kk], vh2);
            }
        }
        __syncthreads();
    }

    // ---- normalize + write O (hi/lo bf16) ----
    float inv[2] = {1.0f / l_i[0], 1.0f / l_i[1]};
    #pragma unroll
    for (int nf = 0; nf < 8; nf++) {
        int col = h * 64 + nf * 8 + (lane & 3) * 2;
        #pragma unroll
        for (int p = 0; p < 2; p++) {
            int row = rq + p * 8;
            float x0 = oacc[nf][2*p+0] * inv[p];
            float x1 = oacc[nf][2*p+1] * inv[p];
            uint32_t lo, hi = packsplit(x0, x1, lo);
            *(uint32_t*)(g_oh + ((size_t)b * SS + row) * DD + col) = hi;
            *(uint32_t*)(g_ol + ((size_t)b * SS + row) * DD + col) = lo;
        }
    }
}

// ---------------------------------------------------------------------------
// Launch
// ---------------------------------------------------------------------------
extern "C" void kernel_launch(void* const* d_in, const int* in_sizes, int n_in,
                              void* d_out, int out_size)
{
    const float* Q     = (const float*)d_in[0];
    const float* K     = (const float*)d_in[1];
    const float* V     = (const float*)d_in[2];
    const int*   mask  = (const int*)  d_in[3];
    const float* abias = (const float*)d_in[4];
    const float* Wq    = (const float*)d_in[5];
    const float* bq    = (const float*)d_in[6];
    const float* Wk    = (const float*)d_in[7];
    const float* bk    = (const float*)d_in[8];
    const float* Wv    = (const float*)d_in[9];
    const float* bv    = (const float*)d_in[10];
    const float* Wo    = (const float*)d_in[11];
    const float* bo    = (const float*)d_in[12];
    float* out = (float*)d_out;

    __nv_bfloat16 *ah, *al, *wh, *wl, *qh, *ql, *kh, *kl, *vh, *vl, *oh, *ol;
    cudaGetSymbolAddress((void**)&ah, g_ah); cudaGetSymbolAddress((void**)&al, g_al);
    cudaGetSymbolAddress((void**)&wh, g_wh); cudaGetSymbolAddress((void**)&wl, g_wl);
    cudaGetSymbolAddress((void**)&qh, g_qh); cudaGetSymbolAddress((void**)&ql, g_ql);
    cudaGetSymbolAddress((void**)&kh, g_kh); cudaGetSymbolAddress((void**)&kl, g_kl);
    cudaGetSymbolAddress((void**)&vh, g_vh); cudaGetSymbolAddress((void**)&vl, g_vl);
    cudaGetSymbolAddress((void**)&oh, g_oh); cudaGetSymbolAddress((void**)&ol, g_ol);

    cudaFuncSetAttribute(gemm3<1>, cudaFuncAttributeMaxDynamicSharedMemorySize, GEMM_SMEM);
    cudaFuncSetAttribute(gemm3<0>, cudaFuncAttributeMaxDynamicSharedMemorySize, GEMM_SMEM);
    cudaFuncSetAttribute(attn3,    cudaFuncAttributeMaxDynamicSharedMemorySize, ATT_SMEM);

    const int nA4 = MM * DD / 4, nW4 = DD * DD / 4;
    dim3 ggrid(DD / 128, MM / 128);

    split_bf16<<<(nA4 + 255) / 256, 256>>>(Q,  ah, al, nA4);
    split_bf16<<<(nW4 + 255) / 256, 256>>>(Wq, wh, wl, nW4);
    gemm3<1><<<ggrid, 256, GEMM_SMEM>>>(ah, al, wh, wl, bq, nullptr, qh, ql);

    split_bf16<<<(nA4 + 255) / 256, 256>>>(K,  ah, al, nA4);
    split_bf16<<<(nW4 + 255) / 256, 256>>>(Wk, wh, wl, nW4);
    gemm3<1><<<ggrid, 256, GEMM_SMEM>>>(ah, al, wh, wl, bk, nullptr, kh, kl);

    split_bf16<<<(nA4 + 255) / 256, 256>>>(V,  ah, al, nA4);
    split_bf16<<<(nW4 + 255) / 256, 256>>>(Wv, wh, wl, nW4);
    gemm3<1><<<ggrid, 256, GEMM_SMEM>>>(ah, al, wh, wl, bv, nullptr, vh, vl);

    attn3<<<dim3(BB * HH, SS / 64), 128, ATT_SMEM>>>(mask, abias);

    split_bf16<<<(nW4 + 255) / 256, 256>>>(Wo, wh, wl, nW4);
    gemm3<0><<<ggrid, 256, GEMM_SMEM>>>(oh, ol, wh, wl, bo, out, nullptr, nullptr);
}

// round 4
// speedup vs baseline: 2.6148x; 1.2559x over previous
#include <cuda_runtime.h>
#include <cuda_bf16.h>
#include <stdint.h>

#define BB 4
#define SS 2048
#define DD 1024
#define HH 16
#define MM (BB*SS)   // 8192

// ---------------------------------------------------------------------------
// Scratch (static device globals; no runtime allocation)
// ---------------------------------------------------------------------------
__device__ __nv_bfloat16 g_ah[MM*DD], g_al[MM*DD];
__device__ __nv_bfloat16 g_wh[DD*DD], g_wl[DD*DD];
__device__ __nv_bfloat16 g_qh[MM*DD], g_ql[MM*DD];
__device__ __nv_bfloat16 g_kh[MM*DD], g_kl[MM*DD];
__device__ __nv_bfloat16 g_vh[MM*DD], g_vl[MM*DD];
__device__ __nv_bfloat16 g_oh[MM*DD], g_ol[MM*DD];

// ---------------------------------------------------------------------------
// PTX helpers
// ---------------------------------------------------------------------------
__device__ __forceinline__ void cpa16(void* s, const void* g) {
    uint32_t sa = (uint32_t)__cvta_generic_to_shared(s);
    asm volatile("cp.async.ca.shared.global [%0], [%1], 16;\n" :: "r"(sa), "l"(g));
}
__device__ __forceinline__ void cp_commit() { asm volatile("cp.async.commit_group;\n" ::); }
template<int N> __device__ __forceinline__ void cp_wait() {
    asm volatile("cp.async.wait_group %0;\n" :: "n"(N));
}
__device__ __forceinline__ void ldsm4(uint32_t* r, const void* p) {
    uint32_t a = (uint32_t)__cvta_generic_to_shared(p);
    asm volatile("ldmatrix.sync.aligned.m8n8.x4.shared.b16 {%0,%1,%2,%3}, [%4];\n"
                 : "=r"(r[0]), "=r"(r[1]), "=r"(r[2]), "=r"(r[3]) : "r"(a));
}
__device__ __forceinline__ void ldsm4t(uint32_t* r, const void* p) {
    uint32_t a = (uint32_t)__cvta_generic_to_shared(p);
    asm volatile("ldmatrix.sync.aligned.m8n8.x4.trans.shared.b16 {%0,%1,%2,%3}, [%4];\n"
                 : "=r"(r[0]), "=r"(r[1]), "=r"(r[2]), "=r"(r[3]) : "r"(a));
}
__device__ __forceinline__ void mma16816(float* c, const uint32_t* a, const uint32_t* b) {
    asm volatile(
        "mma.sync.aligned.m16n8k16.row.col.f32.bf16.bf16.f32 "
        "{%0,%1,%2,%3}, {%4,%5,%6,%7}, {%8,%9}, {%0,%1,%2,%3};\n"
        : "+f"(c[0]), "+f"(c[1]), "+f"(c[2]), "+f"(c[3])
        : "r"(a[0]), "r"(a[1]), "r"(a[2]), "r"(a[3]), "r"(b[0]), "r"(b[1]));
}
__device__ __forceinline__ uint32_t packsplit(float x0, float x1, uint32_t& lo) {
    __nv_bfloat16 h0 = __float2bfloat16(x0), h1 = __float2bfloat16(x1);
    __nv_bfloat16 l0 = __float2bfloat16(x0 - __bfloat162float(h0));
    __nv_bfloat16 l1 = __float2bfloat16(x1 - __bfloat162float(h1));
    __nv_bfloat162 hp = __halves2bfloat162(h0, h1);
    __nv_bfloat162 lp = __halves2bfloat162(l0, l1);
    lo = *(uint32_t*)&lp;
    return *(uint32_t*)&hp;
}

// ---------------------------------------------------------------------------
// fp32 -> bf16 hi/lo split
// ---------------------------------------------------------------------------
__global__ __launch_bounds__(256) void split_bf16(
    const float* __restrict__ x,
    __nv_bfloat16* __restrict__ hi, __nv_bfloat16* __restrict__ lo, int n4)
{
    int i = blockIdx.x * 256 + threadIdx.x;
    if (i >= n4) return;
    float4 v = ((const float4*)x)[i];
    uint32_t l0, l1;
    uint32_t h0 = packsplit(v.x, v.y, l0);
    uint32_t h1 = packsplit(v.z, v.w, l1);
    ((uint32_t*)hi)[i*2+0] = h0; ((uint32_t*)hi)[i*2+1] = h1;
    ((uint32_t*)lo)[i*2+0] = l0; ((uint32_t*)lo)[i*2+1] = l1;
}

// ---------------------------------------------------------------------------
// C[M,1024] = A[M,1024] @ W[1024,1024]^T + bias ; 3-pass split-bf16 tensor GEMM
// ---------------------------------------------------------------------------
#define GST 40
#define GARR (128*GST)
#define GSTAGE (4*GARR)
#define GEMM_SMEM (2*GSTAGE*2)   // 81920 bytes

template<int OUT_BF16>
__global__ __launch_bounds__(256) void gemm3(
    const __nv_bfloat16* __restrict__ Ah, const __nv_bfloat16* __restrict__ Al,
    const __nv_bfloat16* __restrict__ Wh, const __nv_bfloat16* __restrict__ Wl,
    const float* __restrict__ bias, float* __restrict__ C,
    __nv_bfloat16* __restrict__ Ch, __nv_bfloat16* __restrict__ Cl)
{
    extern __shared__ __nv_bfloat16 sg[];
    const int tid = threadIdx.x, lane = tid & 31, warp = tid >> 5;
    const int wm = warp >> 2, wn = warp & 3;
    const int bm = blockIdx.y * 128, bn = blockIdx.x * 128;

    float acc[4][4][4];
    #pragma unroll
    for (int i = 0; i < 4; i++)
        #pragma unroll
        for (int j = 0; j < 4; j++)
            #pragma unroll
            for (int q = 0; q < 4; q++) acc[i][j][q] = 0.0f;

    auto issue = [&](int t, int s) {
        __nv_bfloat16* sb = sg + s * GSTAGE;
        const int k0 = t * 32;
        #pragma unroll
        for (int it = 0; it < 2; it++) {
            int lin = tid + it * 256;
            int r = lin >> 2, c = (lin & 3) * 8;
            size_t ga = (size_t)(bm + r) * DD + k0 + c;
            size_t gw = (size_t)(bn + r) * DD + k0 + c;
            __nv_bfloat16* sr = sb + r * GST + c;
            cpa16(sr,          Ah + ga);
            cpa16(sr + GARR,   Al + ga);
            cpa16(sr + 2*GARR, Wh + gw);
            cpa16(sr + 3*GARR, Wl + gw);
        }
    };

    issue(0, 0); cp_commit();

    for (int t = 0; t < DD / 32; t++) {
        if (t + 1 < DD / 32) { issue(t + 1, (t + 1) & 1); cp_commit(); cp_wait<1>(); }
        else                 { cp_wait<0>(); }
        __syncthreads();

        const __nv_bfloat16* sb = sg + (t & 1) * GSTAGE;
        #pragma unroll
        for (int ks = 0; ks < 2; ks++) {
            uint32_t ah[4][4], al[4][4], bh[4][2], bl[4][2];
            #pragma unroll
            for (int mf = 0; mf < 4; mf++) {
                int r = wm * 64 + mf * 16 + (lane & 15);
                int c = ks * 16 + ((lane >> 4) << 3);
                ldsm4(ah[mf], sb + r * GST + c);
                ldsm4(al[mf], sb + GARR + r * GST + c);
            }
            // B: ldsm4 loads two n8 fragments at once
            #pragma unroll
            for (int nf2 = 0; nf2 < 2; nf2++) {
                uint32_t tr[4];
                int r = wn * 32 + nf2 * 16 + ((lane >> 4) << 3) + (lane & 7);
                int c = ks * 16 + (((lane >> 3) & 1) << 3);
                ldsm4(tr, sb + 2*GARR + r * GST + c);
                bh[nf2*2][0] = tr[0]; bh[nf2*2][1] = tr[1];
                bh[nf2*2+1][0] = tr[2]; bh[nf2*2+1][1] = tr[3];
                ldsm4(tr, sb + 3*GARR + r * GST + c);
                bl[nf2*2][0] = tr[0]; bl[nf2*2][1] = tr[1];
                bl[nf2*2+1][0] = tr[2]; bl[nf2*2+1][1] = tr[3];
            }
            #pragma unroll
            for (int mf = 0; mf < 4; mf++)
                #pragma unroll
                for (int nf = 0; nf < 4; nf++) {
                    mma16816(acc[mf][nf], ah[mf], bh[nf]);
                    mma16816(acc[mf][nf], ah[mf], bl[nf]);
                    mma16816(acc[mf][nf], al[mf], bh[nf]);
                }
        }
        __syncthreads();
    }

    #pragma unroll
    for (int mf = 0; mf < 4; mf++)
        #pragma unroll
        for (int nf = 0; nf < 4; nf++) {
            int col = bn + wn * 32 + nf * 8 + (lane & 3) * 2;
            float2 bs = *(const float2*)(bias + col);
            #pragma unroll
            for (int p = 0; p < 2; p++) {
                int row = bm + wm * 64 + mf * 16 + (lane >> 2) + p * 8;
                float x0 = acc[mf][nf][p*2+0] + bs.x;
                float x1 = acc[mf][nf][p*2+1] + bs.y;
                if (OUT_BF16) {
                    uint32_t lo, hi = packsplit(x0, x1, lo);
                    *(uint32_t*)(Ch + (size_t)row * DD + col) = hi;
                    *(uint32_t*)(Cl + (size_t)row * DD + col) = lo;
                } else {
                    float2 o; o.x = x0; o.y = x1;
                    *(float2*)(C + (size_t)row * DD + col) = o;
                }
            }
        }
}

// ---------------------------------------------------------------------------
// Fused flash attention, split-bf16 tensor cores.
// Block = (b,h) x 128 q-rows, 256 threads = 8 warps (warp = m16 x n64).
// ---------------------------------------------------------------------------
#define AST 72
#define QTILE (128*AST)
#define KTILE (64*AST)
#define ATT_SMEM ((2*QTILE + 8*KTILE) * 2)   // 110592 bytes

__global__ __launch_bounds__(256) void attn3(
    const int* __restrict__ mask, const float* __restrict__ abias)
{
    extern __shared__ __nv_bfloat16 sa[];
    __nv_bfloat16* Qh = sa;
    __nv_bfloat16* Ql = sa + QTILE;

    const int tid = threadIdx.x, lane = tid & 31, warp = tid >> 5;
    const int h = blockIdx.x >> 2, b = blockIdx.x & 3;
    const int q0 = blockIdx.y * 128;
    const float LOG2E = 1.4426950408889634f;

    const size_t qg = ((size_t)b * SS + q0) * DD + h * 64;
    #pragma unroll
    for (int it = 0; it < 4; it++) {
        int lin = tid + it * 256;
        int r = lin >> 3, c = (lin & 7) * 8;
        cpa16(Qh + r * AST + c, g_qh + qg + (size_t)r * DD + c);
        cpa16(Ql + r * AST + c, g_ql + qg + (size_t)r * DD + c);
    }
    auto issue_kv = [&](int kt, int s) {
        __nv_bfloat16* sb = sa + 2 * QTILE + s * 4 * KTILE;
        const size_t g0 = ((size_t)b * SS + kt * 64) * DD + h * 64;
        #pragma unroll
        for (int it = 0; it < 2; it++) {
            int lin = tid + it * 256;
            int r = lin >> 3, c = (lin & 7) * 8;
            size_t g = g0 + (size_t)r * DD + c;
            __nv_bfloat16* sr = sb + r * AST + c;
            cpa16(sr,           g_kh + g);
            cpa16(sr + KTILE,   g_kl + g);
            cpa16(sr + 2*KTILE, g_vh + g);
            cpa16(sr + 3*KTILE, g_vl + g);
        }
    };
    issue_kv(0, 0); cp_commit();

    float oacc[8][4];
    #pragma unroll
    for (int nf = 0; nf < 8; nf++)
        #pragma unroll
        for (int q = 0; q < 4; q++) oacc[nf][q] = 0.0f;
    float m_i[2] = {-1e30f, -1e30f}, l_i[2] = {0.0f, 0.0f};

    const int rq = q0 + warp * 16 + (lane >> 2);

    for (int kt = 0; kt < SS / 64; kt++) {
        if (kt + 1 < SS / 64) { issue_kv(kt + 1, (kt + 1) & 1); cp_commit(); cp_wait<1>(); }
        else                  { cp_wait<0>(); }
        __syncthreads();

        const __nv_bfloat16* Kh = sa + 2 * QTILE + (kt & 1) * 4 * KTILE;
        const __nv_bfloat16* Kl = Kh + KTILE;
        const __nv_bfloat16* Vh = Kh + 2 * KTILE;
        const __nv_bfloat16* Vl = Kh + 3 * KTILE;

        // ---- S = Q K^T (3-pass) ----
        float sacc[8][4];
        #pragma unroll
        for (int nf = 0; nf < 8; nf++)
            #pragma unroll
            for (int q = 0; q < 4; q++) sacc[nf][q] = 0.0f;

        #pragma unroll
        for (int ks = 0; ks < 4; ks++) {
            uint32_t aqh[4], aql[4];
            int rA = warp * 16 + (lane & 15);
            int cA = ks * 16 + ((lane >> 4) << 3);
            ldsm4(aqh, Qh + rA * AST + cA);
            ldsm4(aql, Ql + rA * AST + cA);
            #pragma unroll
            for (int nf2 = 0; nf2 < 4; nf2++) {
                uint32_t kh4[4], kl4[4];
                int rB = nf2 * 16 + ((lane >> 4) << 3) + (lane & 7);
                int cB = ks * 16 + (((lane >> 3) & 1) << 3);
                ldsm4(kh4, Kh + rB * AST + cB);
                ldsm4(kl4, Kl + rB * AST + cB);
                mma16816(sacc[nf2*2],   aqh, kh4);
                mma16816(sacc[nf2*2],   aqh, kl4);
                mma16816(sacc[nf2*2],   aql, kh4);
                mma16816(sacc[nf2*2+1], aqh, kh4 + 2);
                mma16816(sacc[nf2*2+1], aqh, kl4 + 2);
                mma16816(sacc[nf2*2+1], aql, kh4 + 2);
            }
        }

        // ---- mask + bias + online softmax (log2 domain) ----
        const float SC = 0.125f * LOG2E;
        float mx[2] = {-1e30f, -1e30f};
        #pragma unroll
        for (int nf = 0; nf < 8; nf++) {
            int col = kt * 64 + nf * 8 + (lane & 3) * 2;
            #pragma unroll
            for (int p = 0; p < 2; p++) {
                int row = rq + p * 8;
                int2   mr = *(const int2*)  (mask  + ((size_t)b * SS + row) * SS + col);
                float2 br = *(const float2*)(abias + ((size_t)h * SS + row) * SS + col);
                float s0 = fmaf((mr.x != 0 ? sacc[nf][2*p+0] : -8e9f), SC, br.x * LOG2E);
                float s1 = fmaf((mr.y != 0 ? sacc[nf][2*p+1] : -8e9f), SC, br.y * LOG2E);
                sacc[nf][2*p+0] = s0;
                sacc[nf][2*p+1] = s1;
                mx[p] = fmaxf(mx[p], fmaxf(s0, s1));
            }
        }
        float corr[2], ls[2];
        #pragma unroll
        for (int p = 0; p < 2; p++) {
            mx[p] = fmaxf(mx[p], __shfl_xor_sync(0xffffffffu, mx[p], 1));
            mx[p] = fmaxf(mx[p], __shfl_xor_sync(0xffffffffu, mx[p], 2));
            float mn = fmaxf(m_i[p], mx[p]);
            corr[p] = exp2f(m_i[p] - mn);
            m_i[p] = mn;
            ls[p] = 0.0f;
        }
        #pragma unroll
        for (int nf = 0; nf < 8; nf++)
            #pragma unroll
            for (int q = 0; q < 4; q++) {
                float e = exp2f(sacc[nf][q] - m_i[q >> 1]);
                sacc[nf][q] = e;
                ls[q >> 1] += e;
            }
        #pragma unroll
        for (int p = 0; p < 2; p++) {
            ls[p] += __shfl_xor_sync(0xffffffffu, ls[p], 1);
            ls[p] += __shfl_xor_sync(0xffffffffu, ls[p], 2);
            l_i[p] = l_i[p] * corr[p] + ls[p];
        }
        #pragma unroll
        for (int nf = 0; nf < 8; nf++)
            #pragma unroll
            for (int q = 0; q < 4; q++) oacc[nf][q] *= corr[q >> 1];

        // ---- repack P accumulators -> m16k16 A fragments (hi/lo) ----
        uint32_t ph[4][4], pl[4][4];
        #pragma unroll
        for (int kk = 0; kk < 4; kk++) {
            int j = 2 * kk;
            ph[kk][0] = packsplit(sacc[j][0],   sacc[j][1],   pl[kk][0]);
            ph[kk][1] = packsplit(sacc[j][2],   sacc[j][3],   pl[kk][1]);
            ph[kk][2] = packsplit(sacc[j+1][0], sacc[j+1][1], pl[kk][2]);
            ph[kk][3] = packsplit(sacc[j+1][2], sacc[j+1][3], pl[kk][3]);
        }

        // ---- O += P V (3-pass), V fragment pairs via ldsm4t ----
        #pragma unroll
        for (int kk = 0; kk < 4; kk++) {
            int rV = kk * 16 + (((lane >> 3) & 1) << 3) + (lane & 7);
            #pragma unroll
            for (int nf2 = 0; nf2 < 4; nf2++) {
                uint32_t vh4[4], vl4[4];
                int cV = nf2 * 16 + ((lane >> 4) << 3);
                ldsm4t(vh4, Vh + rV * AST + cV);
                ldsm4t(vl4, Vl + rV * AST + cV);
                mma16816(oacc[nf2*2],   ph[kk], vh4);
                mma16816(oacc[nf2*2],   ph[kk], vl4);
                mma16816(oacc[nf2*2],   pl[kk], vh4);
                mma16816(oacc[nf2*2+1], ph[kk], vh4 + 2);
                mma16816(oacc[nf2*2+1], ph[kk], vl4 + 2);
                mma16816(oacc[nf2*2+1], pl[kk], vh4 + 2);
            }
        }
        __syncthreads();
    }

    // ---- normalize + write O (hi/lo bf16) ----
    float inv[2] = {1.0f / l_i[0], 1.0f / l_i[1]};
    #pragma unroll
    for (int nf = 0; nf < 8; nf++) {
        int col = h * 64 + nf * 8 + (lane & 3) * 2;
        #pragma unroll
        for (int p = 0; p < 2; p++) {
            int row = rq + p * 8;
            float x0 = oacc[nf][2*p+0] * inv[p];
            float x1 = oacc[nf][2*p+1] * inv[p];
            uint32_t lo, hi = packsplit(x0, x1, lo);
            *(uint32_t*)(g_oh + ((size_t)b * SS + row) * DD + col) = hi;
            *(uint32_t*)(g_ol + ((size_t)b * SS + row) * DD + col) = lo;
        }
    }
}

// ---------------------------------------------------------------------------
// Launch
// ---------------------------------------------------------------------------
extern "C" void kernel_launch(void* const* d_in, const int* in_sizes, int n_in,
                              void* d_out, int out_size)
{
    const float* Q     = (const float*)d_in[0];
    const float* K     = (const float*)d_in[1];
    const float* V     = (const float*)d_in[2];
    const int*   mask  = (const int*)  d_in[3];
    const float* abias = (const float*)d_in[4];
    const float* Wq    = (const float*)d_in[5];
    const float* bq    = (const float*)d_in[6];
    const float* Wk    = (const float*)d_in[7];
    const float* bk    = (const float*)d_in[8];
    const float* Wv    = (const float*)d_in[9];
    const float* bv    = (const float*)d_in[10];
    const float* Wo    = (const float*)d_in[11];
    const float* bo    = (const float*)d_in[12];
    float* out = (float*)d_out;

    __nv_bfloat16 *ah, *al, *wh, *wl, *qh, *ql, *kh, *kl, *vh, *vl, *oh, *ol;
    cudaGetSymbolAddress((void**)&ah, g_ah); cudaGetSymbolAddress((void**)&al, g_al);
    cudaGetSymbolAddress((void**)&wh, g_wh); cudaGetSymbolAddress((void**)&wl, g_wl);
    cudaGetSymbolAddress((void**)&qh, g_qh); cudaGetSymbolAddress((void**)&ql, g_ql);
    cudaGetSymbolAddress((void**)&kh, g_kh); cudaGetSymbolAddress((void**)&kl, g_kl);
    cudaGetSymbolAddress((void**)&vh, g_vh); cudaGetSymbolAddress((void**)&vl, g_vl);
    cudaGetSymbolAddress((void**)&oh, g_oh); cudaGetSymbolAddress((void**)&ol, g_ol);

    cudaFuncSetAttribute(gemm3<1>, cudaFuncAttributeMaxDynamicSharedMemorySize, GEMM_SMEM);
    cudaFuncSetAttribute(gemm3<0>, cudaFuncAttributeMaxDynamicSharedMemorySize, GEMM_SMEM);
    cudaFuncSetAttribute(attn3,    cudaFuncAttributeMaxDynamicSharedMemorySize, ATT_SMEM);

    const int nA4 = MM * DD / 4, nW4 = DD * DD / 4;
    dim3 ggrid(DD / 128, MM / 128);

    split_bf16<<<(nA4 + 255) / 256, 256>>>(Q,  ah, al, nA4);
    split_bf16<<<(nW4 + 255) / 256, 256>>>(Wq, wh, wl, nW4);
    gemm3<1><<<ggrid, 256, GEMM_SMEM>>>(ah, al, wh, wl, bq, nullptr, qh, ql);

    split_bf16<<<(nA4 + 255) / 256, 256>>>(K,  ah, al, nA4);
    split_bf16<<<(nW4 + 255) / 256, 256>>>(Wk, wh, wl, nW4);
    gemm3<1><<<ggrid, 256, GEMM_SMEM>>>(ah, al, wh, wl, bk, nullptr, kh, kl);

    split_bf16<<<(nA4 + 255) / 256, 256>>>(V,  ah, al, nA4);
    split_bf16<<<(nW4 + 255) / 256, 256>>>(Wv, wh, wl, nW4);
    gemm3<1><<<ggrid, 256, GEMM_SMEM>>>(ah, al, wh, wl, bv, nullptr, vh, vl);

    attn3<<<dim3(BB * HH, SS / 128), 256, ATT_SMEM>>>(mask, abias);

    split_bf16<<<(nW4 + 255) / 256, 256>>>(Wo, wh, wl, nW4);
    gemm3<0><<<ggrid, 256, GEMM_SMEM>>>(oh, ol, wh, wl, bo, out, nullptr, nullptr);
}